// round 11
// baseline (speedup 1.0000x reference)
#include <cuda_runtime.h>

// CWT gaus1, scales {1,3,6}, x:(32,4096,64) f32 -> out:(32,3,4096,64) f32.
//
// Folded form: out_a[b,s,c] = sum_m h_a[m] * x[b, s + start_a + m, c]
//   h_a[m] = -sqrt(a)*(f_a[m-1]-f_a[m]),  f_a[i] = int_psi[floor(i/(a*step))]
// Unified window p in [0,61] rel. to x[s-31]: scale6 m=p (all p), scale3
// m=p-15 for p in [15,46], scale1 m=p-25 for p in [25,36].
//
// R11: persistent blocks + cp.async DOUBLE-BUFFERED tile prefetch. The fill
// for tile k+1 is issued before computing tile k, overlapping the LDG fill
// phase (577cy DRAM) + sync + store drain that kept the fma pipe at 67% in
// R7-R10 despite spare issue slots. Inner loop (per-scale passes, fma.rn.f32x2
// with compile-time packed literals) unchanged from R8. 592 blocks (4/SM),
// 2752 tiles round-robin, TILE_S=48, T=6, regs capped 64 (>= natural ~52).

#define S_LEN   4096
#define C_LEN   64
#define TILE_S  48
#define NROWS   109            // TILE_S + 61
#define NT      256
#define T       6              // seq rows per thread (8 groups x 6 = 48)
#define TPBAT   86             // ceil(4096/48) tiles per batch
#define NTILES  (32 * TPBAT)   // 2752
#define GRIDN   592            // 4 blocks/SM x 148 SMs
#define BUF_F   (NROWS * C_LEN)            // floats per buffer
#define SMEM_BYTES (2 * BUF_F * 4)         // 55808 B

typedef unsigned long long ull;

// ---------------- compile-time coefficient math ----------------
__host__ __device__ constexpr double cpow2i(int n) {
    double r = 1.0;
    if (n >= 0) { for (int i = 0; i <  n; i++) r *= 2.0; }
    else        { for (int i = 0; i < -n; i++) r *= 0.5; }
    return r;
}
__host__ __device__ constexpr double cexp(double x) {
    const double ln2 = 0.6931471805599453;
    int n = (int)(x / ln2 + (x >= 0.0 ? 0.5 : -0.5));
    double r = x - (double)n * ln2;
    double term = 1.0, sum = 1.0;
    for (int k = 1; k <= 20; k++) { term *= r / (double)k; sum += term; }
    return sum * cpow2i(n);
}
__host__ __device__ constexpr double csqrt_(double x) {
    double g = x > 1.0 ? x : 1.0;
    for (int i = 0; i < 64; i++) g = 0.5 * (g + x / g);
    return g;
}
// Euler-Maclaurin model of numpy cumsum(psi)*step for gaus1 (validated at
// rel_err 4e-7 in R1-R10).
__host__ __device__ constexpr double ipsi_em(long j) {
    const double step = 10.0 / 1023.0;
    double u = (j >= 1023) ? 5.0 : ((double)j * step - 5.0);
    double e = cexp(-u * u);
    double v = e * (1.0 - step * u + (step * step / 12.0) * (4.0 * u * u - 2.0));
    return v / csqrt_(csqrt_(3.141592653589793 / 2.0));   // (pi/2)^(1/4)
}
__host__ __device__ constexpr float f_at(int a, int i, int L) {
    if (i < 0 || i >= L) return 0.0f;
    const double step = 10.0 / 1023.0;
    double as_ = (double)a * step;          // matches numpy a*step (f64)
    long j = (long)((double)i / as_);       // matches arange/(a*step) astype(int64)
    return (float)ipsi_em(j);
}
__host__ __device__ constexpr float hval(int a, int L, int m) {
    float fm1 = f_at(a, m - 1, L), fm = f_at(a, m, L);
    return -(float)csqrt_((double)a) * (fm1 - fm);   // f32 math like reference
}
// exact constexpr float->bits (taps are normal floats, mantissa integer-exact)
__host__ __device__ constexpr unsigned int f2b(float v) {
    if (v == 0.0f) return 0u;
    unsigned int s = 0; double a = (double)v;
    if (a < 0.0) { s = 0x80000000u; a = -a; }
    int e = 0;
    while (a >= 2.0) { a *= 0.5; e++; }
    while (a < 1.0)  { a *= 2.0; e--; }
    unsigned long long m = (unsigned long long)(a * 8388608.0);  // exact
    return s | ((unsigned int)(e + 127) << 23) | ((unsigned int)m & 0x7FFFFFu);
}
__host__ __device__ constexpr ull pk(float v) {
    unsigned int b = f2b(v);
    return ((ull)b << 32) | (ull)b;
}

__device__ __forceinline__ void ffma2(ull &d, ull a, ull b) {
    asm("fma.rn.f32x2 %0, %1, %2, %0;" : "+l"(d) : "l"(a), "l"(b));
}
__device__ __forceinline__ unsigned smem_u32(const void* p) {
    unsigned a;
    asm("{ .reg .u64 t; cvta.to.shared.u64 t, %1; cvt.u32.u64 %0, t; }"
        : "=r"(a) : "l"(p));
    return a;
}
__device__ __forceinline__ void cp_async16(unsigned d, const void* g) {
    asm volatile("cp.async.ca.shared.global [%0], [%1], 16;"
                 :: "r"(d), "l"(g) : "memory");
}

// ---------------- async tile fill (zero-padded at seq edges) ----------------
__device__ __forceinline__ void fill_tile(unsigned sbase, const float4* xg,
                                          int s0m31, int tid) {
    #pragma unroll
    for (int k = 0; k < 7; k++) {
        int f = tid + k * NT;
        if (f < NROWS * 16) {
            int gs = s0m31 + (f >> 4);
            unsigned d = sbase + f * 16;
            if (gs >= 0 && gs < S_LEN)
                cp_async16(d, (const void*)(xg + gs * 16 + (f & 15)));
            else
                asm volatile("st.shared.v4.b32 [%0], {%1,%1,%1,%1};"
                             :: "r"(d), "r"(0) : "memory");
        }
    }
}

// ---------------- one pass over taps of a single scale ----------------
// Ring of 8 rows: at iter P holds rows P..P+7, uses P..P+5, prefetches row
// P+7 (consumed at iter P+2).
template<int P, int P0, int PEND, int A, int L>
__device__ __forceinline__ void pass_step(const float (*xs)[C_LEN], int rbase, int pr,
                                          ull (&win)[8], ull (&Acc)[T]) {
    if constexpr (P < PEND) {
        if constexpr (P + 7 <= PEND + 4)   // rows needed go up to PEND-1+5
            win[(P + 7) % 8] = *(const ull*)&xs[rbase + P + 7][pr * 2];
        constexpr ull c = pk(hval(A, L, P - P0));
        #pragma unroll
        for (int t = 0; t < T; t++)
            ffma2(Acc[t], win[(P + t) % 8], c);
        pass_step<P + 1, P0, PEND, A, L>(xs, rbase, pr, win, Acc);
    }
}

template<int P0, int PEND, int A, int L>
__device__ __forceinline__ void do_pass(const float (*xs)[C_LEN], int rbase, int pr,
                                        ull (&Acc)[T]) {
    ull win[8];
    #pragma unroll
    for (int r = 0; r < 7; r++)
        win[(P0 + r) % 8] = *(const ull*)&xs[rbase + P0 + r][pr * 2];
    pass_step<P0, P0, PEND, A, L>(xs, rbase, pr, win, Acc);
}

// ---------------- kernel ----------------
__global__ void __launch_bounds__(NT, 4)
cwt_kernel(const float* __restrict__ x, float* __restrict__ out) {
    extern __shared__ float smem_raw[];

    const int tid = threadIdx.x;
    const int pr    = tid & 31;          // channel pair 0..31
    const int sg    = tid >> 5;          // seq group 0..7
    const int rbase = sg * T;
    const size_t plane = (size_t)S_LEN * (C_LEN / 2);
    const unsigned sb0 = smem_u32(smem_raw);

    // prologue: async-fill buffer 0 with this block's first tile
    int tile = blockIdx.x;               // < NTILES (592 < 2752)
    {
        int b = tile / TPBAT, ts = tile - b * TPBAT;
        const float4* xg = (const float4*)x + (size_t)b * (S_LEN * 16);
        fill_tile(sb0, xg, ts * TILE_S - 31, tid);
    }
    asm volatile("cp.async.commit_group;" ::: "memory");

    int cur = 0;
    for (; tile < NTILES; tile += GRIDN) {
        asm volatile("cp.async.wait_group 0;" ::: "memory");
        __syncthreads();   // buffer `cur` ready; all warps done with `cur^1`

        // issue async fill of the NEXT tile into the other buffer
        int nt = tile + GRIDN;
        if (nt < NTILES) {
            int nb = nt / TPBAT, nts = nt - nb * TPBAT;
            const float4* nxg = (const float4*)x + (size_t)nb * (S_LEN * 16);
            fill_tile(sb0 + (cur ^ 1) * (BUF_F * 4), nxg, nts * TILE_S - 31, tid);
        }
        asm volatile("cp.async.commit_group;" ::: "memory");

        // compute current tile
        int b = tile / TPBAT, ts = tile - b * TPBAT;
        int s0 = ts * TILE_S;
        const float (*xs)[C_LEN] =
            (const float (*)[C_LEN])(smem_raw + cur * BUF_F);
        ull* og = (ull*)out + (size_t)b * 3 * S_LEN * (C_LEN / 2);
        const int srow = s0 + rbase;

        {   // scale 6: taps p = 0..61
            ull A6[T] = {0,0,0,0,0,0};
            do_pass<0, 62, 6, 61>(xs, rbase, pr, A6);
            #pragma unroll
            for (int t = 0; t < T; t++)
                if (srow + t < S_LEN)
                    og[2 * plane + (size_t)(srow + t) * (C_LEN / 2) + pr] = A6[t];
        }
        {   // scale 3: taps p = 15..46
            ull A3[T] = {0,0,0,0,0,0};
            do_pass<15, 47, 3, 31>(xs, rbase, pr, A3);
            #pragma unroll
            for (int t = 0; t < T; t++)
                if (srow + t < S_LEN)
                    og[1 * plane + (size_t)(srow + t) * (C_LEN / 2) + pr] = A3[t];
        }
        {   // scale 1: taps p = 25..36
            ull A1[T] = {0,0,0,0,0,0};
            do_pass<25, 37, 1, 11>(xs, rbase, pr, A1);
            #pragma unroll
            for (int t = 0; t < T; t++)
                if (srow + t < S_LEN)
                    og[0 * plane + (size_t)(srow + t) * (C_LEN / 2) + pr] = A1[t];
        }

        cur ^= 1;
        __syncthreads();   // all reads of `cur` done before it is refilled
    }
}

extern "C" void kernel_launch(void* const* d_in, const int* in_sizes, int n_in,
                              void* d_out, int out_size) {
    const float* x = (const float*)d_in[0];
    float* out = (float*)d_out;
    cudaFuncSetAttribute(cwt_kernel,
                         cudaFuncAttributeMaxDynamicSharedMemorySize, SMEM_BYTES);
    cwt_kernel<<<GRIDN, NT, SMEM_BYTES>>>(x, out);
}

// round 13
// speedup vs baseline: 1.3876x; 1.3876x over previous
#include <cuda_runtime.h>

// CWT gaus1, scales {1,3,6}, x:(32,4096,64) f32 -> out:(32,3,4096,64) f32.
//
// Folded form: out_a[b,s,c] = sum_m h_a[m] * x[b, s + start_a + m, c]
//   h_a[m] = -sqrt(a)*(f_a[m-1]-f_a[m]),  f_a[i] = int_psi[floor(i/(a*step))]
// Unified window p in [0,61] rel. to x[s-31]: scale6 m=p (all p), scale3
// m=p-15 for p in [15,46], scale1 m=p-25 for p in [25,36].
//
// R13 = R8 inner math (per-scale passes, fma.rn.f32x2, compile-time packed
// reg constants) with SMEM REMOVED: each warp's row load is already a fully
// coalesced 256B LDG (lanes = channel pairs), rows reuse 8x through L1
// (39cy hits; input is L2-resident across graph replays). Kills the
// fill->syncthreads->compute phase serialization that held fma at 67% in
// R7-R11. Loads are LDG.64 [ptr+imm] (compile-time row offsets). Edge tiles
// (s0=0, s0=4032) take a predicated template path; interior is branch-free.

#define S_LEN 4096
#define C_LEN 64
#define TILE_S 64
#define NT 256
#define T 8         // seq rows per thread

typedef unsigned long long ull;

// ---------------- compile-time coefficient math ----------------
__host__ __device__ constexpr double cpow2i(int n) {
    double r = 1.0;
    if (n >= 0) { for (int i = 0; i <  n; i++) r *= 2.0; }
    else        { for (int i = 0; i < -n; i++) r *= 0.5; }
    return r;
}
__host__ __device__ constexpr double cexp(double x) {
    const double ln2 = 0.6931471805599453;
    int n = (int)(x / ln2 + (x >= 0.0 ? 0.5 : -0.5));
    double r = x - (double)n * ln2;
    double term = 1.0, sum = 1.0;
    for (int k = 1; k <= 20; k++) { term *= r / (double)k; sum += term; }
    return sum * cpow2i(n);
}
__host__ __device__ constexpr double csqrt_(double x) {
    double g = x > 1.0 ? x : 1.0;
    for (int i = 0; i < 64; i++) g = 0.5 * (g + x / g);
    return g;
}
// Euler-Maclaurin model of numpy cumsum(psi)*step for gaus1 (validated at
// rel_err 4e-7 in R1-R12).
__host__ __device__ constexpr double ipsi_em(long j) {
    const double step = 10.0 / 1023.0;
    double u = (j >= 1023) ? 5.0 : ((double)j * step - 5.0);
    double e = cexp(-u * u);
    double v = e * (1.0 - step * u + (step * step / 12.0) * (4.0 * u * u - 2.0));
    return v / csqrt_(csqrt_(3.141592653589793 / 2.0));   // (pi/2)^(1/4)
}
__host__ __device__ constexpr float f_at(int a, int i, int L) {
    if (i < 0 || i >= L) return 0.0f;
    const double step = 10.0 / 1023.0;
    double as_ = (double)a * step;          // matches numpy a*step (f64)
    long j = (long)((double)i / as_);       // matches arange/(a*step) astype(int64)
    return (float)ipsi_em(j);
}
__host__ __device__ constexpr float hval(int a, int L, int m) {
    float fm1 = f_at(a, m - 1, L), fm = f_at(a, m, L);
    return -(float)csqrt_((double)a) * (fm1 - fm);   // f32 math like reference
}
// exact constexpr float->bits (taps are normal floats, mantissa integer-exact)
__host__ __device__ constexpr unsigned int f2b(float v) {
    if (v == 0.0f) return 0u;
    unsigned int s = 0; double a = (double)v;
    if (a < 0.0) { s = 0x80000000u; a = -a; }
    int e = 0;
    while (a >= 2.0) { a *= 0.5; e++; }
    while (a < 1.0)  { a *= 2.0; e--; }
    unsigned long long m = (unsigned long long)(a * 8388608.0);  // exact
    return s | ((unsigned int)(e + 127) << 23) | ((unsigned int)m & 0x7FFFFFu);
}
__host__ __device__ constexpr ull pk(float v) {
    unsigned int b = f2b(v);
    return ((ull)b << 32) | (ull)b;
}

__device__ __forceinline__ void ffma2(ull &d, ull a, ull b) {
    asm("fma.rn.f32x2 %0, %1, %2, %0;" : "+l"(d) : "l"(a), "l"(b));
}

// row r (relative to this thread's window base): 8B load, coalesced per warp.
// EDGE: predicated to 0 outside [0, S_LEN).
template<bool EDGE>
__device__ __forceinline__ ull load_row(const float* base, int g0, int r) {
    ull v = 0;
    if (!EDGE || (unsigned)(g0 + r) < (unsigned)S_LEN)
        v = *(const ull*)(base + (size_t)r * C_LEN);
    return v;
}

// ---------------- one pass over taps of a single scale ----------------
// Ring of 12 rows: at iter P holds rows P..P+11 (uses P..P+7); prefetch row
// P+11 at iter P, first consumed at iter P+4 (~100 issue slots of cover).
template<int P, int P0, int PEND, int A, int L, bool EDGE>
__device__ __forceinline__ void pass_step(const float* base, int g0,
                                          ull (&win)[12], ull (&Acc)[T]) {
    if constexpr (P < PEND) {
        if constexpr (P + 11 <= PEND + 6)   // rows needed go up to PEND-1+7
            win[(P + 11) % 12] = load_row<EDGE>(base, g0, P + 11);
        constexpr ull c = pk(hval(A, L, P - P0));
        #pragma unroll
        for (int t = 0; t < T; t++)
            ffma2(Acc[t], win[(P + t) % 12], c);
        pass_step<P + 1, P0, PEND, A, L, EDGE>(base, g0, win, Acc);
    }
}

template<int P0, int PEND, int A, int L, bool EDGE>
__device__ __forceinline__ void do_pass(const float* base, int g0, ull (&Acc)[T]) {
    ull win[12];
    #pragma unroll
    for (int r = 0; r < 11; r++)
        win[(P0 + r) % 12] = load_row<EDGE>(base, g0, P0 + r);
    pass_step<P0, P0, PEND, A, L, EDGE>(base, g0, win, Acc);
}

template<bool EDGE>
__device__ __forceinline__ void compute_tile(const float* base, int g0,
                                             ull* og, int srow, int pr) {
    const size_t plane = (size_t)S_LEN * (C_LEN / 2);
    {   // scale 6: taps p = 0..61
        ull A6[T] = {0,0,0,0,0,0,0,0};
        do_pass<0, 62, 6, 61, EDGE>(base, g0, A6);
        #pragma unroll
        for (int t = 0; t < T; t++)
            og[2 * plane + (size_t)(srow + t) * (C_LEN / 2) + pr] = A6[t];
    }
    {   // scale 3: taps p = 15..46
        ull A3[T] = {0,0,0,0,0,0,0,0};
        do_pass<15, 47, 3, 31, EDGE>(base, g0, A3);
        #pragma unroll
        for (int t = 0; t < T; t++)
            og[1 * plane + (size_t)(srow + t) * (C_LEN / 2) + pr] = A3[t];
    }
    {   // scale 1: taps p = 25..36
        ull A1[T] = {0,0,0,0,0,0,0,0};
        do_pass<25, 37, 1, 11, EDGE>(base, g0, A1);
        #pragma unroll
        for (int t = 0; t < T; t++)
            og[0 * plane + (size_t)(srow + t) * (C_LEN / 2) + pr] = A1[t];
    }
}

// ---------------- kernel ----------------
__global__ void __launch_bounds__(NT)
cwt_kernel(const float* __restrict__ x, float* __restrict__ out) {
    const int tid = threadIdx.x;
    const int b   = blockIdx.y;
    const int s0  = blockIdx.x * TILE_S;

    const int pr    = tid & 31;          // channel pair 0..31 (lane)
    const int sg    = tid >> 5;          // seq group 0..7 (warp)
    const int rbase = sg * T;

    const int g0 = s0 - 31 + rbase;      // global seq index of window row 0
    const float* base = x + (size_t)b * S_LEN * C_LEN
                          + (size_t)g0 * C_LEN + pr * 2;
    ull* og = (ull*)out + (size_t)b * 3 * S_LEN * (C_LEN / 2);
    const int srow = s0 + rbase;

    if (s0 == 0 || s0 == S_LEN - TILE_S)
        compute_tile<true >(base, g0, og, srow, pr);
    else
        compute_tile<false>(base, g0, og, srow, pr);
}

extern "C" void kernel_launch(void* const* d_in, const int* in_sizes, int n_in,
                              void* d_out, int out_size) {
    const float* x = (const float*)d_in[0];
    float* out = (float*)d_out;
    dim3 grid(S_LEN / TILE_S, 32);   // (64 seq tiles, 32 batches)
    cwt_kernel<<<grid, NT>>>(x, out);
}

// round 14
// speedup vs baseline: 1.9483x; 1.4041x over previous
#include <cuda_runtime.h>

// CWT gaus1, scales {1,3,6}, x:(32,4096,64) f32 -> out:(32,3,4096,64) f32.
//
// Folded form: out_a[b,s,c] = sum_m h_a[m] * x[b, s + start_a + m, c]
//   h_a[m] = -sqrt(a)*(f_a[m-1]-f_a[m]),  f_a[i] = int_psi[floor(i/(a*step))]
// Unified window p in [0,61] rel. to x[s-31]: scale6 m=p (all p), scale3
// m=p-15 for p in [15,46], scale1 m=p-25 for p in [25,36].
//
// R14 = R8 (best: per-scale passes, fma.rn.f32x2 with compile-time packed
// reg constants, NT=256/TILE_S=64, no reg cap) + TAP TRUNCATION: the filter
// is psi(u) = -2u e^{-u^2}(..) sampled over u in [-5,5]; taps beyond
// |u|~3.8 are < 3e-6 of the peak. Tolerance is 1e-3 and we sit at 4e-7, so
// the Gaussian tails are dropped (contiguous -> pass ranges narrow):
//   scale6: m in [8,53] (46 of 62), scale3: m in [4,26] (24 of 32),
//   scale1: m in [2,8] (8 of 12).  78 vs 106 taps = -26% FFMA2 pipe work.

#define S_LEN 4096
#define C_LEN 64
#define TILE_S 64
#define NROWS 125   // TILE_S + 61
#define NT 256
#define T 8         // seq rows per thread

typedef unsigned long long ull;

// ---------------- compile-time coefficient math ----------------
__host__ __device__ constexpr double cpow2i(int n) {
    double r = 1.0;
    if (n >= 0) { for (int i = 0; i <  n; i++) r *= 2.0; }
    else        { for (int i = 0; i < -n; i++) r *= 0.5; }
    return r;
}
__host__ __device__ constexpr double cexp(double x) {
    const double ln2 = 0.6931471805599453;
    int n = (int)(x / ln2 + (x >= 0.0 ? 0.5 : -0.5));
    double r = x - (double)n * ln2;
    double term = 1.0, sum = 1.0;
    for (int k = 1; k <= 20; k++) { term *= r / (double)k; sum += term; }
    return sum * cpow2i(n);
}
__host__ __device__ constexpr double csqrt_(double x) {
    double g = x > 1.0 ? x : 1.0;
    for (int i = 0; i < 64; i++) g = 0.5 * (g + x / g);
    return g;
}
// Euler-Maclaurin model of numpy cumsum(psi)*step for gaus1 (validated at
// rel_err 4e-7 in R1-R13).
__host__ __device__ constexpr double ipsi_em(long j) {
    const double step = 10.0 / 1023.0;
    double u = (j >= 1023) ? 5.0 : ((double)j * step - 5.0);
    double e = cexp(-u * u);
    double v = e * (1.0 - step * u + (step * step / 12.0) * (4.0 * u * u - 2.0));
    return v / csqrt_(csqrt_(3.141592653589793 / 2.0));   // (pi/2)^(1/4)
}
__host__ __device__ constexpr float f_at(int a, int i, int L) {
    if (i < 0 || i >= L) return 0.0f;
    const double step = 10.0 / 1023.0;
    double as_ = (double)a * step;          // matches numpy a*step (f64)
    long j = (long)((double)i / as_);       // matches arange/(a*step) astype(int64)
    return (float)ipsi_em(j);
}
__host__ __device__ constexpr float hval(int a, int L, int m) {
    float fm1 = f_at(a, m - 1, L), fm = f_at(a, m, L);
    return -(float)csqrt_((double)a) * (fm1 - fm);   // f32 math like reference
}
// exact constexpr float->bits (taps are normal floats, mantissa integer-exact)
__host__ __device__ constexpr unsigned int f2b(float v) {
    if (v == 0.0f) return 0u;
    unsigned int s = 0; double a = (double)v;
    if (a < 0.0) { s = 0x80000000u; a = -a; }
    int e = 0;
    while (a >= 2.0) { a *= 0.5; e++; }
    while (a < 1.0)  { a *= 2.0; e--; }
    unsigned long long m = (unsigned long long)(a * 8388608.0);  // exact
    return s | ((unsigned int)(e + 127) << 23) | ((unsigned int)m & 0x7FFFFFu);
}
__host__ __device__ constexpr ull pk(float v) {
    unsigned int b = f2b(v);
    return ((ull)b << 32) | (ull)b;
}

__device__ __forceinline__ void ffma2(ull &d, ull a, ull b) {
    asm("fma.rn.f32x2 %0, %1, %2, %0;" : "+l"(d) : "l"(a), "l"(b));
}

// ---------------- one pass over a (truncated) tap range ----------------
// P = unified window index; filter tap index m = P - F0. Ring of 10 rows:
// at iter P holds rows P..P+9 (mod 10), uses rows P..P+7, prefetches row
// P+9 (consumed at iter P+2).
template<int P, int F0, int PEND, int A, int L>
__device__ __forceinline__ void pass_step(const float (*xs)[C_LEN], int rbase, int pr,
                                          ull (&win)[10], ull (&Acc)[T]) {
    if constexpr (P < PEND) {
        if constexpr (P + 9 <= PEND + 6)   // rows needed go up to PEND-1+7
            win[(P + 9) % 10] = *(const ull*)&xs[rbase + P + 9][pr * 2];
        constexpr ull c = pk(hval(A, L, P - F0));
        #pragma unroll
        for (int t = 0; t < T; t++)
            ffma2(Acc[t], win[(P + t) % 10], c);
        pass_step<P + 1, F0, PEND, A, L>(xs, rbase, pr, win, Acc);
    }
}

template<int PSTART, int F0, int PEND, int A, int L>
__device__ __forceinline__ void do_pass(const float (*xs)[C_LEN], int rbase, int pr,
                                        ull (&Acc)[T]) {
    ull win[10];
    #pragma unroll
    for (int r = 0; r < 9; r++)
        win[(PSTART + r) % 10] = *(const ull*)&xs[rbase + PSTART + r][pr * 2];
    pass_step<PSTART, F0, PEND, A, L>(xs, rbase, pr, win, Acc);
}

// ---------------- kernel ----------------
__global__ void __launch_bounds__(NT)
cwt_kernel(const float* __restrict__ x, float* __restrict__ out) {
    __shared__ float xs[NROWS][C_LEN];

    const int tid = threadIdx.x;
    const int b   = blockIdx.y;
    const int s0  = blockIdx.x * TILE_S;

    // ---- fill smem tile (rows s0-31 .. s0+93, zero-padded at edges) ----
    const float4* xg = (const float4*)x + (size_t)b * (S_LEN * (C_LEN / 4));
    const float4 z4 = make_float4(0.f, 0.f, 0.f, 0.f);
    #pragma unroll
    for (int k = 0; k < 8; k++) {
        int f = tid + k * NT;
        if (f < NROWS * 16) {
            int row = f >> 4, q = f & 15;
            int gs = s0 - 31 + row;
            float4 v = (gs >= 0 && gs < S_LEN) ? xg[gs * 16 + q] : z4;
            *(float4*)&xs[row][q * 4] = v;
        }
    }
    __syncthreads();

    // ---- compute: thread = 2 channels x 8 seq rows, one scale per pass ----
    const int pr    = tid & 31;          // channel pair 0..31
    const int sg    = tid >> 5;          // seq group 0..7
    const int rbase = sg * T;

    ull* og = (ull*)out + (size_t)b * 3 * S_LEN * (C_LEN / 2);
    const int srow = s0 + rbase;
    const size_t plane = (size_t)S_LEN * (C_LEN / 2);

    {   // scale 6: full taps m=0..61; kept m in [8,53] -> P in [8,54)
        ull A6[T] = {0,0,0,0,0,0,0,0};
        do_pass<8, 0, 54, 6, 61>(xs, rbase, pr, A6);
        #pragma unroll
        for (int t = 0; t < T; t++)
            og[2 * plane + (size_t)(srow + t) * (C_LEN / 2) + pr] = A6[t];
    }
    {   // scale 3: full taps m=0..31 at P=m+15; kept m in [4,26] -> P in [19,42)
        ull A3[T] = {0,0,0,0,0,0,0,0};
        do_pass<19, 15, 42, 3, 31>(xs, rbase, pr, A3);
        #pragma unroll
        for (int t = 0; t < T; t++)
            og[1 * plane + (size_t)(srow + t) * (C_LEN / 2) + pr] = A3[t];
    }
    {   // scale 1: full taps m=0..11 at P=m+25; kept m in [2,8] -> P in [27,34)
        ull A1[T] = {0,0,0,0,0,0,0,0};
        do_pass<27, 25, 34, 1, 11>(xs, rbase, pr, A1);
        #pragma unroll
        for (int t = 0; t < T; t++)
            og[0 * plane + (size_t)(srow + t) * (C_LEN / 2) + pr] = A1[t];
    }
}

extern "C" void kernel_launch(void* const* d_in, const int* in_sizes, int n_in,
                              void* d_out, int out_size) {
    const float* x = (const float*)d_in[0];
    float* out = (float*)d_out;
    dim3 grid(S_LEN / TILE_S, 32);   // (64 seq tiles, 32 batches)
    cwt_kernel<<<grid, NT>>>(x, out);
}